// round 3
// baseline (speedup 1.0000x reference)
#include <cuda_runtime.h>
#include <cstdint>

// Problem dims (fixed by the dataset)
#define Bv 8
#define Cv 64
#define Hv 256
#define Wv 256
#define HW (Hv * Wv)          // 65536
#define CI_CHUNK 4
#define XS_PITCH 264
#define EPSV 1e-5f

// ---------------- scratch (no allocations allowed) ----------------
__device__ float g_colsum[Bv * Cv * Wv];   // sum over h of x  [b,c,w]
__device__ float g_fsum[Bv * Cv];
__device__ float g_scores[Bv * Cv];

// ---------------- f32x2 helpers ----------------
__device__ __forceinline__ unsigned long long pk2(float lo, float hi) {
    unsigned long long r;
    asm("mov.b64 %0, {%1, %2};" : "=l"(r) : "f"(lo), "f"(hi));
    return r;
}
__device__ __forceinline__ void unpk2(unsigned long long v, float& lo, float& hi) {
    asm("mov.b64 {%0, %1}, %2;" : "=f"(lo), "=f"(hi) : "l"(v));
}
__device__ __forceinline__ unsigned long long fma2(unsigned long long a,
                                                   unsigned long long b,
                                                   unsigned long long c) {
    unsigned long long d;
    asm("fma.rn.f32x2 %0, %1, %2, %3;" : "=l"(d) : "l"(a), "l"(b), "l"(c));
    return d;
}

// ---------------- kernel 1: column sums of x ----------------
__global__ void k_colsum(const float* __restrict__ x) {
    int bc = blockIdx.x;
    int w = threadIdx.x;
    const float* p = x + (size_t)bc * HW + w;
    float s0 = 0.f, s1 = 0.f, s2 = 0.f, s3 = 0.f;
    #pragma unroll 4
    for (int h = 0; h < Hv; h += 4) {
        s0 += p[(h + 0) * Wv];
        s1 += p[(h + 1) * Wv];
        s2 += p[(h + 2) * Wv];
        s3 += p[(h + 3) * Wv];
    }
    g_colsum[bc * Wv + w] = (s0 + s1) + (s2 + s3);
}

// ---------------- kernel 2: f_sum via row-sum identity ----------------
__global__ void k_fsum(const float* __restrict__ x,
                       const float* __restrict__ wq,
                       const float* __restrict__ wk) {
    int c = blockIdx.x, b = blockIdx.y;
    int w = threadIdx.x;
    __shared__ float wqs[576];
    __shared__ float wks[576];
    __shared__ float red[256];
    for (int i = threadIdx.x; i < 576; i += 256) {
        wqs[i] = wq[c * 576 + i];
        wks[i] = wk[c * 576 + i];
    }
    __syncthreads();

    float sq = 0.f, sk = 0.f;
    for (int ci = 0; ci < Cv; ci++) {
        const float* Sc = g_colsum + (b * Cv + ci) * Wv;
        const float* xf = x + (size_t)(b * Cv + ci) * HW;           // row 0
        const float* xl = xf + (Hv - 1) * Wv;                       // row H-1
        const float* q9 = wqs + ci * 9;
        const float* K9 = wks + ci * 9;
        #pragma unroll
        for (int dw = 0; dw < 3; dw++) {
            int wp = w + dw - 1;
            if ((unsigned)wp < (unsigned)Wv) {
                float s = Sc[wp], t = xl[wp], f = xf[wp];
                float q0 = q9[dw], q1 = q9[3 + dw], q2 = q9[6 + dw];
                float k0 = K9[dw], k1 = K9[3 + dw], k2 = K9[6 + dw];
                sq += s * (q0 + q1 + q2) - t * q0 - f * q2;
                sk += s * (k0 + k1 + k2) - t * k0 - f * k2;
            }
        }
    }
    red[w] = sq * sk;
    __syncthreads();
    for (int s = 128; s > 0; s >>= 1) {
        if (w < s) red[w] += red[w + s];
        __syncthreads();
    }
    if (w == 0) g_fsum[b * Cv + c] = red[0] * 0.0625f;   // 1/sqrt(256)
}

// ---------------- kernel 3: softmax over channels ----------------
__global__ void k_softmax() {
    int b = blockIdx.x, t = threadIdx.x;
    __shared__ float sm[64];
    float v = g_fsum[b * Cv + t];
    sm[t] = v;
    __syncthreads();
    for (int s = 32; s > 0; s >>= 1) {
        if (t < s) sm[t] = fmaxf(sm[t], sm[t + s]);
        __syncthreads();
    }
    float m = sm[0];
    __syncthreads();
    float e = expf(v - m);
    sm[t] = e;
    __syncthreads();
    for (int s = 32; s > 0; s >>= 1) {
        if (t < s) sm[t] += sm[t + s];
        __syncthreads();
    }
    g_scores[b * Cv + t] = e / sm[0];
}

// ---------------- kernel 4: fused conv3x3(wv) + epilogue ----------------
// Block: one (b, h-pair). 512 threads: tx=lane covers w=8*tx..8*tx+7,
// ty=0..15 -> couts ty*4..ty*4+3. Two output rows per block share the two
// interior input rows (each x LDS.128 feeds both output rows).
// Weights stored duplicated (w,w) in smem so one broadcast LDS.128 yields
// two couts' f32x2 operands.
__global__ void __launch_bounds__(512, 1)
k_convv(const float* __restrict__ x,
        const float* __restrict__ wv,
        const float* __restrict__ gamma,
        const float* __restrict__ beta,
        const float* __restrict__ rmean,
        const float* __restrict__ rvar,
        float* __restrict__ out) {
    __shared__ float xs[CI_CHUNK][4][XS_PITCH];        // [ci][row][col 0..257], col=w+1
    __shared__ float ws[CI_CHUNK * 9 * 128];           // [(ci*9+dh*3+dw)*128 + 2*cout] dup pairs

    const int h0 = blockIdx.x * 2;
    const int b = blockIdx.y;
    const int tid = threadIdx.x;
    const int tx = tid & 31;
    const int ty = tid >> 5;
    const int cbase = ty * 4;

    unsigned long long acc[2][4][4];   // [outrow][cout][w-pair]
    #pragma unroll
    for (int o = 0; o < 2; o++)
        #pragma unroll
        for (int k = 0; k < 4; k++)
            #pragma unroll
            for (int p = 0; p < 4; p++) acc[o][k][p] = 0ull;

    for (int cc = 0; cc < Cv / CI_CHUNK; cc++) {
        __syncthreads();
        // ---- x tile: CI_CHUNK ci x 4 rows x 258 cols (zero-padded) ----
        for (int idx = tid; idx < CI_CHUNK * 4 * 258; idx += 512) {
            int ci = idx / (4 * 258);
            int rem = idx - ci * (4 * 258);
            int r = rem / 258;
            int col = rem - r * 258;
            int hr = h0 + r - 1;
            float v = 0.f;
            if (col >= 1 && col <= 256 && hr >= 0 && hr < Hv)
                v = x[((size_t)(b * Cv + cc * CI_CHUNK + ci) * Hv + hr) * Wv + (col - 1)];
            xs[ci][r][col] = v;
        }
        // ---- weights, duplicated pairs: ws[r9*128 + 2*cout] = {w,w} ----
        for (int idx = tid; idx < CI_CHUNK * 9 * 64; idx += 512) {
            int cout = idx & 63;
            int r9 = idx >> 6;                   // ci*9 + dh*3 + dw
            int ci = r9 / 9;
            int k9 = r9 - ci * 9;
            float wval = wv[(size_t)cout * (Cv * 9) + (cc * CI_CHUNK + ci) * 9 + k9];
            *(float2*)&ws[r9 * 128 + 2 * cout] = make_float2(wval, wval);
        }
        __syncthreads();

        #pragma unroll 1
        for (int ci = 0; ci < CI_CHUNK; ci++) {
            #pragma unroll
            for (int rr = 0; rr < 4; rr++) {
                const float* xrow = &xs[ci][rr][0];
                float4 A  = *(const float4*)(xrow + 8 * tx);
                float4 Bq = *(const float4*)(xrow + 8 * tx + 4);
                float4 Cq = *(const float4*)(xrow + 8 * tx + 8);
                float r_[10] = {A.x, A.y, A.z, A.w, Bq.x, Bq.y, Bq.z, Bq.w, Cq.x, Cq.y};
                unsigned long long v[9];
                #pragma unroll
                for (int j = 0; j < 9; j++) v[j] = pk2(r_[j], r_[j + 1]);

                // out row 0 uses this input row with dh = rr (rr<3)
                if (rr < 3) {
                    const float* wb = &ws[(ci * 9 + rr * 3) * 128 + 2 * cbase];
                    #pragma unroll
                    for (int dw = 0; dw < 3; dw++) {
                        ulonglong2 W01 = *(const ulonglong2*)(wb + dw * 128);
                        ulonglong2 W23 = *(const ulonglong2*)(wb + dw * 128 + 4);
                        #pragma unroll
                        for (int p = 0; p < 4; p++) {
                            acc[0][0][p] = fma2(v[2 * p + dw], W01.x, acc[0][0][p]);
                            acc[0][1][p] = fma2(v[2 * p + dw], W01.y, acc[0][1][p]);
                            acc[0][2][p] = fma2(v[2 * p + dw], W23.x, acc[0][2][p]);
                            acc[0][3][p] = fma2(v[2 * p + dw], W23.y, acc[0][3][p]);
                        }
                    }
                }
                // out row 1 uses this input row with dh = rr-1 (rr>=1)
                if (rr >= 1) {
                    const float* wb = &ws[(ci * 9 + (rr - 1) * 3) * 128 + 2 * cbase];
                    #pragma unroll
                    for (int dw = 0; dw < 3; dw++) {
                        ulonglong2 W01 = *(const ulonglong2*)(wb + dw * 128);
                        ulonglong2 W23 = *(const ulonglong2*)(wb + dw * 128 + 4);
                        #pragma unroll
                        for (int p = 0; p < 4; p++) {
                            acc[1][0][p] = fma2(v[2 * p + dw], W01.x, acc[1][0][p]);
                            acc[1][1][p] = fma2(v[2 * p + dw], W01.y, acc[1][1][p]);
                            acc[1][2][p] = fma2(v[2 * p + dw], W23.x, acc[1][2][p]);
                            acc[1][3][p] = fma2(v[2 * p + dw], W23.y, acc[1][3][p]);
                        }
                    }
                }
            }
        }
    }

    // ---- epilogue: relu( (score*inv)*fv + inv*x + (beta - mean*inv) ) ----
    #pragma unroll
    for (int o = 0; o < 2; o++) {
        int h = h0 + o;
        #pragma unroll
        for (int k = 0; k < 4; k++) {
            int c = cbase + k;
            float inv = gamma[c] * rsqrtf(rvar[c] + EPSV);
            float alpha = g_scores[b * Cv + c] * inv;
            float bias = beta[c] - rmean[c] * inv;
            const float* xrow = x + ((size_t)(b * Cv + c) * Hv + h) * Wv;
            float* orow = out + ((size_t)(b * Cv + c) * Hv + h) * Wv;
            #pragma unroll
            for (int g = 0; g < 2; g++) {       // two float4 groups: pairs (2g, 2g+1)
                float f0lo, f0hi, f1lo, f1hi;
                unpk2(acc[o][k][2 * g + 0], f0lo, f0hi);
                unpk2(acc[o][k][2 * g + 1], f1lo, f1hi);
                int w0 = 8 * tx + 4 * g;
                float4 xr = *(const float4*)(xrow + w0);
                float4 ov;
                ov.x = fmaxf(fmaf(alpha, f0lo, fmaf(inv, xr.x, bias)), 0.f);
                ov.y = fmaxf(fmaf(alpha, f0hi, fmaf(inv, xr.y, bias)), 0.f);
                ov.z = fmaxf(fmaf(alpha, f1lo, fmaf(inv, xr.z, bias)), 0.f);
                ov.w = fmaxf(fmaf(alpha, f1hi, fmaf(inv, xr.w, bias)), 0.f);
                *(float4*)(orow + w0) = ov;
            }
        }
    }
}

// ---------------- launch ----------------
extern "C" void kernel_launch(void* const* d_in, const int* in_sizes, int n_in,
                              void* d_out, int out_size) {
    const float* x     = (const float*)d_in[0];
    const float* wq    = (const float*)d_in[1];
    const float* wk    = (const float*)d_in[2];
    const float* wv    = (const float*)d_in[3];
    const float* gamma = (const float*)d_in[4];
    const float* beta  = (const float*)d_in[5];
    const float* rmean = (const float*)d_in[6];
    const float* rvar  = (const float*)d_in[7];
    float* out = (float*)d_out;

    k_colsum<<<Bv * Cv, 256>>>(x);
    k_fsum<<<dim3(Cv, Bv), 256>>>(x, wq, wk);
    k_softmax<<<Bv, 64>>>();
    k_convv<<<dim3(Hv / 2, Bv), 512>>>(x, wv, gamma, beta, rmean, rvar, out);
}

// round 4
// speedup vs baseline: 1.1776x; 1.1776x over previous
#include <cuda_runtime.h>
#include <cstdint>

// Problem dims (fixed by the dataset)
#define Bv 8
#define Cv 64
#define Hv 256
#define Wv 256
#define HW (Hv * Wv)          // 65536
#define CI_CHUNK 8
#define XS_PITCH 264          // 3 pad | 1 left halo | 256 main | 1 right halo | 3 pad
#define WS_STAGE (CI_CHUNK * 9 * 128)          // 9216 floats per stage
#define XS_STAGE (CI_CHUNK * 4 * XS_PITCH)     // 8448 floats per stage
#define SMEM_FLOATS (2 * (WS_STAGE + XS_STAGE))
#define SMEM_BYTES (SMEM_FLOATS * 4)           // 141312 B
#define EPSV 1e-5f

// ---------------- scratch (no allocations allowed) ----------------
__device__ float g_colsum[Bv * Cv * Wv];   // sum over h of x  [b,c,w]
__device__ float g_fsum[Bv * Cv];
__device__ float g_scores[Bv * Cv];
__device__ float g_wdup[Cv * 9 * 128];     // [(ci*9+k9)*128 + 2*cout] = {w,w}

// ---------------- f32x2 helpers ----------------
__device__ __forceinline__ unsigned long long pk2(float lo, float hi) {
    unsigned long long r;
    asm("mov.b64 %0, {%1, %2};" : "=l"(r) : "f"(lo), "f"(hi));
    return r;
}
__device__ __forceinline__ void unpk2(unsigned long long v, float& lo, float& hi) {
    asm("mov.b64 {%0, %1}, %2;" : "=f"(lo), "=f"(hi) : "l"(v));
}
__device__ __forceinline__ unsigned long long fma2(unsigned long long a,
                                                   unsigned long long b,
                                                   unsigned long long c) {
    unsigned long long d;
    asm("fma.rn.f32x2 %0, %1, %2, %3;" : "=l"(d) : "l"(a), "l"(b), "l"(c));
    return d;
}

// ---------------- cp.async helpers ----------------
__device__ __forceinline__ void cp16(uint32_t dst, const void* src, int srcbytes) {
    asm volatile("cp.async.cg.shared.global [%0], [%1], 16, %2;\n"
                 :: "r"(dst), "l"(src), "r"(srcbytes));
}
__device__ __forceinline__ void cp_commit() {
    asm volatile("cp.async.commit_group;\n" ::: "memory");
}
template <int N>
__device__ __forceinline__ void cp_wait() {
    asm volatile("cp.async.wait_group %0;\n" :: "n"(N) : "memory");
}

// ---------------- kernel 0: pre-transform wv into dup-pair layout ----------------
// g_wdup[(ci*9+k9)*128 + 2*cout] = {wv[cout][ci][k9], same}
__global__ void k_wprep(const float* __restrict__ wv) {
    int r9 = blockIdx.x;          // ci*9 + k9, 0..575
    int cout = threadIdx.x;       // 0..63
    float v = wv[(size_t)cout * 576 + r9];
    *(float2*)&g_wdup[r9 * 128 + 2 * cout] = make_float2(v, v);
}

// ---------------- kernel 1: column sums of x ----------------
__global__ void k_colsum(const float* __restrict__ x) {
    int bc = blockIdx.x;
    int w = threadIdx.x;
    const float* p = x + (size_t)bc * HW + w;
    float s0 = 0.f, s1 = 0.f, s2 = 0.f, s3 = 0.f;
    #pragma unroll 4
    for (int h = 0; h < Hv; h += 4) {
        s0 += p[(h + 0) * Wv];
        s1 += p[(h + 1) * Wv];
        s2 += p[(h + 2) * Wv];
        s3 += p[(h + 3) * Wv];
    }
    g_colsum[bc * Wv + w] = (s0 + s1) + (s2 + s3);
}

// ---------------- kernel 2: f_sum via row-sum identity ----------------
__global__ void k_fsum(const float* __restrict__ x,
                       const float* __restrict__ wq,
                       const float* __restrict__ wk) {
    int c = blockIdx.x, b = blockIdx.y;
    int w = threadIdx.x;
    __shared__ float wqs[576];
    __shared__ float wks[576];
    __shared__ float red[256];
    for (int i = threadIdx.x; i < 576; i += 256) {
        wqs[i] = wq[c * 576 + i];
        wks[i] = wk[c * 576 + i];
    }
    __syncthreads();

    float sq = 0.f, sk = 0.f;
    for (int ci = 0; ci < Cv; ci++) {
        const float* Sc = g_colsum + (b * Cv + ci) * Wv;
        const float* xf = x + (size_t)(b * Cv + ci) * HW;           // row 0
        const float* xl = xf + (Hv - 1) * Wv;                       // row H-1
        const float* q9 = wqs + ci * 9;
        const float* K9 = wks + ci * 9;
        #pragma unroll
        for (int dw = 0; dw < 3; dw++) {
            int wp = w + dw - 1;
            if ((unsigned)wp < (unsigned)Wv) {
                float s = Sc[wp], t = xl[wp], f = xf[wp];
                float q0 = q9[dw], q1 = q9[3 + dw], q2 = q9[6 + dw];
                float k0 = K9[dw], k1 = K9[3 + dw], k2 = K9[6 + dw];
                sq += s * (q0 + q1 + q2) - t * q0 - f * q2;
                sk += s * (k0 + k1 + k2) - t * k0 - f * k2;
            }
        }
    }
    red[w] = sq * sk;
    __syncthreads();
    for (int s = 128; s > 0; s >>= 1) {
        if (w < s) red[w] += red[w + s];
        __syncthreads();
    }
    if (w == 0) g_fsum[b * Cv + c] = red[0] * 0.0625f;   // 1/sqrt(256)
}

// ---------------- kernel 3: softmax over channels ----------------
__global__ void k_softmax() {
    int b = blockIdx.x, t = threadIdx.x;
    __shared__ float sm[64];
    float v = g_fsum[b * Cv + t];
    sm[t] = v;
    __syncthreads();
    for (int s = 32; s > 0; s >>= 1) {
        if (t < s) sm[t] = fmaxf(sm[t], sm[t + s]);
        __syncthreads();
    }
    float m = sm[0];
    __syncthreads();
    float e = expf(v - m);
    sm[t] = e;
    __syncthreads();
    for (int s = 32; s > 0; s >>= 1) {
        if (t < s) sm[t] += sm[t + s];
        __syncthreads();
    }
    g_scores[b * Cv + t] = e / sm[0];
}

// ---------------- kernel 4: fused conv3x3(wv) + epilogue, cp.async pipelined ----------------
// Block: one (b, h-pair). 512 threads: tx=lane covers w=8*tx..8*tx+7,
// ty=0..15 -> couts ty*4..ty*4+3. Double-buffered x/w tiles via cp.async.
// x smem row layout (pitch 264): idx 3 = w-1 halo (const 0), idx 4..259 = w 0..255,
// idx 260 = w=256 halo (const 0). Main region 16B-aligned for LDGSTS.
__global__ void __launch_bounds__(512, 1)
k_convv(const float* __restrict__ x,
        const float* __restrict__ gamma,
        const float* __restrict__ beta,
        const float* __restrict__ rmean,
        const float* __restrict__ rvar,
        float* __restrict__ out) {
    extern __shared__ float smem[];
    float* xs = smem;                         // [2][CI_CHUNK][4][XS_PITCH]
    float* ws = smem + 2 * XS_STAGE;          // [2][WS_STAGE]

    const int h0 = blockIdx.x * 2;
    const int b = blockIdx.y;
    const int tid = threadIdx.x;
    const int tx = tid & 31;
    const int ty = tid >> 5;
    const int cbase = ty * 4;

    // ---- one-time halo zeroing (both stages; never overwritten) ----
    if (tid < 2 * CI_CHUNK * 4) {
        float* row = xs + tid * XS_PITCH;
        row[3] = 0.f;
        row[260] = 0.f;
    }

    // ---- per-thread load geometry ----
    const int rowid = tid >> 4;      // 0..31  -> (ci, r)
    const int q16 = tid & 15;
    const int lci = rowid >> 2;
    const int lr = rowid & 3;
    const int hr = h0 + lr - 1;
    const int okbytes = (hr >= 0 && hr < Hv) ? 16 : 0;
    const int hsafe = (okbytes ? hr : 0);

    auto issue_load = [&](int stage, int cc) {
        // x tile: 8 ci x 4 rows x 256 main cols, 4 float4 per thread
        const float* src = x + ((size_t)(b * Cv + cc * CI_CHUNK + lci) * Hv + hsafe) * Wv;
        float* dstrow = xs + (size_t)stage * XS_STAGE + (lci * 4 + lr) * XS_PITCH + 4;
        #pragma unroll
        for (int j = 0; j < 4; j++) {
            int k = q16 + 16 * j;                 // float4 index 0..63
            uint32_t d = (uint32_t)__cvta_generic_to_shared(dstrow + 4 * k);
            cp16(d, src + 4 * k, okbytes);
        }
        // weight slice: 2304 float4
        const float4* wsrc = (const float4*)(g_wdup + (size_t)cc * WS_STAGE);
        float4* wdst = (float4*)(ws + (size_t)stage * WS_STAGE);
        for (int i = tid; i < WS_STAGE / 4; i += 512) {
            uint32_t d = (uint32_t)__cvta_generic_to_shared(wdst + i);
            cp16(d, wsrc + i, 16);
        }
    };

    unsigned long long acc[2][4][4];   // [outrow][cout][w-pair]
    #pragma unroll
    for (int o = 0; o < 2; o++)
        #pragma unroll
        for (int k = 0; k < 4; k++)
            #pragma unroll
            for (int p = 0; p < 4; p++) acc[o][k][p] = 0ull;

    // ---- pipeline prologue ----
    issue_load(0, 0);
    cp_commit();

    #pragma unroll 1
    for (int cc = 0; cc < Cv / CI_CHUNK; cc++) {
        const int stage = cc & 1;
        __syncthreads();                          // prev compute on (stage^1) done
        if (cc + 1 < Cv / CI_CHUNK) {
            issue_load(stage ^ 1, cc + 1);
            cp_commit();
            cp_wait<1>();                         // stage `cc` data arrived
        } else {
            cp_wait<0>();
        }
        __syncthreads();

        const float* xsb = xs + (size_t)stage * XS_STAGE;
        const float* wsb = ws + (size_t)stage * WS_STAGE;

        #pragma unroll 1
        for (int ci = 0; ci < CI_CHUNK; ci++) {
            #pragma unroll
            for (int rr = 0; rr < 4; rr++) {
                const float* xrow = xsb + (ci * 4 + rr) * XS_PITCH + 3 + 8 * tx;
                float r0 = xrow[0];
                float4 A = *(const float4*)(xrow + 1);
                float4 Bq = *(const float4*)(xrow + 5);
                float r9f = xrow[9];
                float r_[10] = {r0, A.x, A.y, A.z, A.w, Bq.x, Bq.y, Bq.z, Bq.w, r9f};
                unsigned long long v[9];
                #pragma unroll
                for (int j = 0; j < 9; j++) v[j] = pk2(r_[j], r_[j + 1]);

                // out row 0 uses this input row with dh = rr (rr<3)
                if (rr < 3) {
                    const float* wb = wsb + (ci * 9 + rr * 3) * 128 + 2 * cbase;
                    #pragma unroll
                    for (int dw = 0; dw < 3; dw++) {
                        ulonglong2 W01 = *(const ulonglong2*)(wb + dw * 128);
                        ulonglong2 W23 = *(const ulonglong2*)(wb + dw * 128 + 4);
                        #pragma unroll
                        for (int p = 0; p < 4; p++) {
                            acc[0][0][p] = fma2(v[2 * p + dw], W01.x, acc[0][0][p]);
                            acc[0][1][p] = fma2(v[2 * p + dw], W01.y, acc[0][1][p]);
                            acc[0][2][p] = fma2(v[2 * p + dw], W23.x, acc[0][2][p]);
                            acc[0][3][p] = fma2(v[2 * p + dw], W23.y, acc[0][3][p]);
                        }
                    }
                }
                // out row 1 uses this input row with dh = rr-1 (rr>=1)
                if (rr >= 1) {
                    const float* wb = wsb + (ci * 9 + (rr - 1) * 3) * 128 + 2 * cbase;
                    #pragma unroll
                    for (int dw = 0; dw < 3; dw++) {
                        ulonglong2 W01 = *(const ulonglong2*)(wb + dw * 128);
                        ulonglong2 W23 = *(const ulonglong2*)(wb + dw * 128 + 4);
                        #pragma unroll
                        for (int p = 0; p < 4; p++) {
                            acc[1][0][p] = fma2(v[2 * p + dw], W01.x, acc[1][0][p]);
                            acc[1][1][p] = fma2(v[2 * p + dw], W01.y, acc[1][1][p]);
                            acc[1][2][p] = fma2(v[2 * p + dw], W23.x, acc[1][2][p]);
                            acc[1][3][p] = fma2(v[2 * p + dw], W23.y, acc[1][3][p]);
                        }
                    }
                }
            }
        }
    }

    // ---- epilogue: relu( (score*inv)*fv + inv*x + (beta - mean*inv) ) ----
    #pragma unroll
    for (int o = 0; o < 2; o++) {
        int h = h0 + o;
        #pragma unroll
        for (int k = 0; k < 4; k++) {
            int c = cbase + k;
            float inv = gamma[c] * rsqrtf(rvar[c] + EPSV);
            float alpha = g_scores[b * Cv + c] * inv;
            float bias = beta[c] - rmean[c] * inv;
            const float* xrow = x + ((size_t)(b * Cv + c) * Hv + h) * Wv;
            float* orow = out + ((size_t)(b * Cv + c) * Hv + h) * Wv;
            #pragma unroll
            for (int g = 0; g < 2; g++) {       // two float4 groups: pairs (2g, 2g+1)
                float f0lo, f0hi, f1lo, f1hi;
                unpk2(acc[o][k][2 * g + 0], f0lo, f0hi);
                unpk2(acc[o][k][2 * g + 1], f1lo, f1hi);
                int w0 = 8 * tx + 4 * g;
                float4 xr = *(const float4*)(xrow + w0);
                float4 ov;
                ov.x = fmaxf(fmaf(alpha, f0lo, fmaf(inv, xr.x, bias)), 0.f);
                ov.y = fmaxf(fmaf(alpha, f0hi, fmaf(inv, xr.y, bias)), 0.f);
                ov.z = fmaxf(fmaf(alpha, f1lo, fmaf(inv, xr.z, bias)), 0.f);
                ov.w = fmaxf(fmaf(alpha, f1hi, fmaf(inv, xr.w, bias)), 0.f);
                *(float4*)(orow + w0) = ov;
            }
        }
    }
}

// ---------------- launch ----------------
extern "C" void kernel_launch(void* const* d_in, const int* in_sizes, int n_in,
                              void* d_out, int out_size) {
    const float* x     = (const float*)d_in[0];
    const float* wq    = (const float*)d_in[1];
    const float* wk    = (const float*)d_in[2];
    const float* wv    = (const float*)d_in[3];
    const float* gamma = (const float*)d_in[4];
    const float* beta  = (const float*)d_in[5];
    const float* rmean = (const float*)d_in[6];
    const float* rvar  = (const float*)d_in[7];
    float* out = (float*)d_out;

    cudaFuncSetAttribute(k_convv, cudaFuncAttributeMaxDynamicSharedMemorySize,
                         SMEM_BYTES);

    k_wprep<<<576, 64>>>(wv);
    k_colsum<<<Bv * Cv, 256>>>(x);
    k_fsum<<<dim3(Cv, Bv), 256>>>(x, wq, wk);
    k_softmax<<<Bv, 64>>>();
    k_convv<<<dim3(Hv / 2, Bv), 512, SMEM_BYTES>>>(x, gamma, beta, rmean, rvar, out);
}